// round 3
// baseline (speedup 1.0000x reference)
#include <cuda_runtime.h>
#include <stdint.h>

// Problem constants (fixed shapes from reference setup_inputs)
#define B_  16
#define C_  3
#define H_  1024
#define W_  1024
#define CP  35                 // 1024/32 + 3
#define CP_HALF 17.0f          // (CP-1)/2
#define CP_ELEMS (2*CP*CP)     // 2450 floats

__global__ __launch_bounds__(256)
void bspline_kernel(const float* __restrict__ x,
                    const float* __restrict__ cp,
                    float* __restrict__ out)
{
    __shared__ float s_cp[CP_ELEMS];

    const int tid = threadIdx.x;
    // cooperative load of control points (9.8 KB) into shared
    #pragma unroll
    for (int t = tid; t < CP_ELEMS; t += 256)
        s_cp[t] = cp[t];
    __syncthreads();

    const int j = blockIdx.x * 256 + tid;   // column
    const int i = blockIdx.y;               // row
    const int b = blockIdx.z;               // batch
    if (j >= W_) return;

    // normalized grid coords (align_corners linspace -1..1)
    const float gx = -1.0f + 2.0f * (float)j / (float)(W_ - 1);
    const float gy = -1.0f + 2.0f * (float)i / (float)(H_ - 1);

    // ---- stage 1: bilinear sample of control points (border padding) ----
    // cp_grid values (absolute-ish coords fed to grid_sample as if normalized)
    const float cpx = gx * CP_HALF + CP_HALF;
    const float cpy = gy * CP_HALF + CP_HALF;
    // grid_sample mapping with its own W=H=CP, align_corners=True
    float cix = (cpx + 1.0f) * 0.5f * (float)(CP - 1);
    float ciy = (cpy + 1.0f) * 0.5f * (float)(CP - 1);
    cix = fminf(fmaxf(cix, 0.0f), (float)(CP - 1));
    ciy = fminf(fmaxf(ciy, 0.0f), (float)(CP - 1));
    const float cix0f = floorf(cix);
    const float ciy0f = floorf(ciy);
    const float cwx = cix - cix0f;
    const float cwy = ciy - ciy0f;
    const int cix0 = (int)cix0f;
    const int ciy0 = (int)ciy0f;
    const int cix1 = min(cix0 + 1, CP - 1);
    const int ciy1 = min(ciy0 + 1, CP - 1);

    const int o00 = ciy0 * CP + cix0;
    const int o01 = ciy0 * CP + cix1;
    const int o10 = ciy1 * CP + cix0;
    const int o11 = ciy1 * CP + cix1;

    float df0, df1;
    {
        // channel 0
        const float v00 = s_cp[o00], v01 = s_cp[o01];
        const float v10 = s_cp[o10], v11 = s_cp[o11];
        const float top = v00 * (1.0f - cwx) + v01 * cwx;
        const float bot = v10 * (1.0f - cwx) + v11 * cwx;
        df0 = top * (1.0f - cwy) + bot * cwy;
    }
    {
        // channel 1
        const float v00 = s_cp[CP*CP + o00], v01 = s_cp[CP*CP + o01];
        const float v10 = s_cp[CP*CP + o10], v11 = s_cp[CP*CP + o11];
        const float top = v00 * (1.0f - cwx) + v01 * cwx;
        const float bot = v10 * (1.0f - cwx) + v11 * cwx;
        df1 = top * (1.0f - cwy) + bot * cwy;
    }

    // b==0 blocks also emit the deformation_field output (2, H, W)
    if (b == 0) {
        float* df_out = out + (size_t)B_ * C_ * H_ * W_;
        df_out[(size_t)i * W_ + j]              = df0;
        df_out[(size_t)H_ * W_ + (size_t)i * W_ + j] = df1;
    }

    // ---- stage 2: bilinear sample of x at (gx+df1, gy+df0), border ----
    const float sx = gx + df1;
    const float sy = gy + df0;
    float ix = (sx + 1.0f) * 0.5f * (float)(W_ - 1);
    float iy = (sy + 1.0f) * 0.5f * (float)(H_ - 1);
    ix = fminf(fmaxf(ix, 0.0f), (float)(W_ - 1));
    iy = fminf(fmaxf(iy, 0.0f), (float)(H_ - 1));
    const float ix0f = floorf(ix);
    const float iy0f = floorf(iy);
    const float wx = ix - ix0f;
    const float wy = iy - iy0f;
    const int ix0 = (int)ix0f;
    const int iy0 = (int)iy0f;
    const int ix1 = min(ix0 + 1, W_ - 1);
    const int iy1 = min(iy0 + 1, H_ - 1);

    const float w00 = (1.0f - wx) * (1.0f - wy);
    const float w01 = wx * (1.0f - wy);
    const float w10 = (1.0f - wx) * wy;
    const float w11 = wx * wy;

    const size_t plane = (size_t)H_ * W_;
    const size_t r0 = (size_t)iy0 * W_;
    const size_t r1 = (size_t)iy1 * W_;

    const float* xb = x + (size_t)b * C_ * plane;
    float* ob = out + (size_t)b * C_ * plane + (size_t)i * W_ + j;

    #pragma unroll
    for (int c = 0; c < C_; c++) {
        const float* xp = xb + (size_t)c * plane;
        const float v00 = __ldg(xp + r0 + ix0);
        const float v01 = __ldg(xp + r0 + ix1);
        const float v10 = __ldg(xp + r1 + ix0);
        const float v11 = __ldg(xp + r1 + ix1);
        ob[c * plane] = v00 * w00 + v01 * w01 + v10 * w10 + v11 * w11;
    }
}

extern "C" void kernel_launch(void* const* d_in, const int* in_sizes, int n_in,
                              void* d_out, int out_size)
{
    const float* x  = (const float*)d_in[0];         // (16,3,1024,1024)
    const float* cp = (const float*)d_in[1];         // (1,2,35,35)
    float* out = (float*)d_out;                      // transformed ++ deformation_field

    dim3 block(256, 1, 1);
    dim3 grid(W_ / 256, H_, B_);
    bspline_kernel<<<grid, block>>>(x, cp, out);
}

// round 4
// speedup vs baseline: 1.1946x; 1.1946x over previous
#include <cuda_runtime.h>
#include <stdint.h>

// Fixed shapes from reference setup_inputs
#define B_  16
#define C_  3
#define H_  1024
#define W_  1024
#define CP  35                 // 1024/32 + 3
#define CP_HALF 17.0f          // (CP-1)/2
#define CP_ELEMS (2*CP*CP)     // 2450 floats
#define PLANE (H_*W_)          // 1<<20

// ---------------------------------------------------------------------------
// Kernel A: compute deformation field (2, H, W) once and write it to the
// df region of the output. This is batch-invariant work and df is itself a
// required output, so this is (nearly) free.
// ---------------------------------------------------------------------------
__global__ __launch_bounds__(256)
void df_kernel(const float* __restrict__ cp, float* __restrict__ df_out)
{
    __shared__ float s_cp[CP_ELEMS];
    const int tid = threadIdx.x;
    #pragma unroll
    for (int t = tid; t < CP_ELEMS; t += 256)
        s_cp[t] = cp[t];
    __syncthreads();

    const int j = blockIdx.x * 256 + tid;
    const int i = blockIdx.y;

    const float gx = -1.0f + 2.0f * (float)j * (1.0f / (float)(W_ - 1));
    const float gy = -1.0f + 2.0f * (float)i * (1.0f / (float)(H_ - 1));

    // grid_sample of control points, align_corners=True, border padding
    const float cpx = gx * CP_HALF + CP_HALF;
    const float cpy = gy * CP_HALF + CP_HALF;
    float cix = (cpx + 1.0f) * 0.5f * (float)(CP - 1);
    float ciy = (cpy + 1.0f) * 0.5f * (float)(CP - 1);
    cix = fminf(fmaxf(cix, 0.0f), (float)(CP - 1));
    ciy = fminf(fmaxf(ciy, 0.0f), (float)(CP - 1));
    const float cix0f = floorf(cix);
    const float ciy0f = floorf(ciy);
    const float cwx = cix - cix0f;
    const float cwy = ciy - ciy0f;
    const int cix0 = (int)cix0f;
    const int ciy0 = (int)ciy0f;
    const int cix1 = min(cix0 + 1, CP - 1);
    const int ciy1 = min(ciy0 + 1, CP - 1);

    const int o00 = ciy0 * CP + cix0;
    const int o01 = ciy0 * CP + cix1;
    const int o10 = ciy1 * CP + cix0;
    const int o11 = ciy1 * CP + cix1;

    float df0, df1;
    {
        const float v00 = s_cp[o00], v01 = s_cp[o01];
        const float v10 = s_cp[o10], v11 = s_cp[o11];
        const float top = v00 * (1.0f - cwx) + v01 * cwx;
        const float bot = v10 * (1.0f - cwx) + v11 * cwx;
        df0 = top * (1.0f - cwy) + bot * cwy;
    }
    {
        const float v00 = s_cp[CP*CP + o00], v01 = s_cp[CP*CP + o01];
        const float v10 = s_cp[CP*CP + o10], v11 = s_cp[CP*CP + o11];
        const float top = v00 * (1.0f - cwx) + v01 * cwx;
        const float bot = v10 * (1.0f - cwx) + v11 * cwx;
        df1 = top * (1.0f - cwy) + bot * cwy;
    }

    const int p = i * W_ + j;
    df_out[p]         = df0;
    df_out[PLANE + p] = df1;
}

// ---------------------------------------------------------------------------
// Kernel B: per-batch bilinear gather of x using the precomputed df.
// df (8 MB) stays L2-resident across all 16 batches.
// ---------------------------------------------------------------------------
__global__ __launch_bounds__(256)
void warp_kernel(const float* __restrict__ x,
                 const float* __restrict__ df,
                 float* __restrict__ out)
{
    const int j = blockIdx.x * 256 + threadIdx.x;
    const int i = blockIdx.y;
    const int b = blockIdx.z;
    const int p = i * W_ + j;

    const float df0 = __ldg(df + p);
    const float df1 = __ldg(df + PLANE + p);

    const float gx = -1.0f + 2.0f * (float)j * (1.0f / (float)(W_ - 1));
    const float gy = -1.0f + 2.0f * (float)i * (1.0f / (float)(H_ - 1));

    // grid_sample of x at (gx+df1, gy+df0), align_corners=True, border padding
    float ix = (gx + df1 + 1.0f) * 0.5f * (float)(W_ - 1);
    float iy = (gy + df0 + 1.0f) * 0.5f * (float)(H_ - 1);
    ix = fminf(fmaxf(ix, 0.0f), (float)(W_ - 1));
    iy = fminf(fmaxf(iy, 0.0f), (float)(H_ - 1));
    const float ix0f = floorf(ix);
    const float iy0f = floorf(iy);
    const float wx = ix - ix0f;
    const float wy = iy - iy0f;
    const int ix0 = (int)ix0f;
    const int iy0 = (int)iy0f;
    const int dx = (ix0 + 1 <= W_ - 1) ? 1 : 0;       // ix1 - ix0
    const int dyw = (iy0 + 1 <= H_ - 1) ? W_ : 0;     // (iy1 - iy0)*W

    const float w00 = (1.0f - wx) * (1.0f - wy);
    const float w01 = wx * (1.0f - wy);
    const float w10 = (1.0f - wx) * wy;
    const float w11 = wx * wy;

    const int base = iy0 * W_ + ix0;                  // fits in int (< 2^20)
    const float* xb = x + (size_t)(b * C_) * PLANE;
    float* ob = out + (size_t)(b * C_) * PLANE + p;

    #pragma unroll
    for (int c = 0; c < C_; c++) {
        const float* xp = xb + (size_t)c * PLANE;
        const float v00 = __ldg(xp + base);
        const float v01 = __ldg(xp + base + dx);
        const float v10 = __ldg(xp + base + dyw);
        const float v11 = __ldg(xp + base + dyw + dx);
        ob[(size_t)c * PLANE] = v00 * w00 + v01 * w01 + v10 * w10 + v11 * w11;
    }
}

extern "C" void kernel_launch(void* const* d_in, const int* in_sizes, int n_in,
                              void* d_out, int out_size)
{
    const float* x  = (const float*)d_in[0];    // (16,3,1024,1024)
    const float* cp = (const float*)d_in[1];    // (1,2,35,35)
    float* out = (float*)d_out;                 // transformed (48M) ++ df (2M)
    float* df  = out + (size_t)B_ * C_ * PLANE;

    dim3 block(256, 1, 1);
    df_kernel<<<dim3(W_ / 256, H_, 1), block>>>(cp, df);
    warp_kernel<<<dim3(W_ / 256, H_, B_), block>>>(x, df, out);
}